// round 17
// baseline (speedup 1.0000x reference)
#include <cuda_runtime.h>
#include <math.h>

#define FULL 0xffffffffu

typedef unsigned long long u64;

// ---- packed fp32x2 helpers (sm_100+; ptxas never auto-fuses these) ----
__device__ __forceinline__ u64 pack2(float lo, float hi) {
    u64 r; asm("mov.b64 %0,{%1,%2};" : "=l"(r) : "f"(lo), "f"(hi)); return r;
}
__device__ __forceinline__ float2 unpack2(u64 v) {
    float2 f; asm("mov.b64 {%0,%1},%2;" : "=f"(f.x), "=f"(f.y) : "l"(v)); return f;
}
__device__ __forceinline__ u64 fma2(u64 a, u64 b, u64 c) {
    u64 d; asm("fma.rn.f32x2 %0,%1,%2,%3;" : "=l"(d) : "l"(a), "l"(b), "l"(c)); return d;
}
__device__ __forceinline__ u64 mul2(u64 a, u64 b) {
    u64 d; asm("mul.rn.f32x2 %0,%1,%2;" : "=l"(d) : "l"(a), "l"(b)); return d;
}
__device__ __forceinline__ u64 add2(u64 a, u64 b) {
    u64 d; asm("add.rn.f32x2 %0,%1,%2;" : "=l"(d) : "l"(a), "l"(b)); return d;
}

// DUAL-MATRIX Jacobi round: two independent 32x32 problems per warp give the
// scheduler a second ready stream inside the warp (mat2's SHFL/dot overlap
// mat1's serial MUFU angle chain). Fast scaled rotations, per-sweep-refreshed
// incremental norms (R7 lesson), division-free gamma bookkeeping:
//   stored' = stored + coef*partner, coef = tOwn*gam_partner*rgam_own,
//   gam *= c, rgam *= h1*c   (c = rsqrt(h1), 1/c = h1*c).
// Both lanes of a pair see bitwise-identical rawdot/gam products -> identical
// rotation without an extra exchange.
template<bool TRACK>
__device__ __forceinline__ void jacobi_round2(
    u64 (&A1)[16], u64 (&A2)[16],
    float& n1, float& n2, float& g1, float& g2, float& rg1, float& rg2,
    int lane, int& jj, int& p31, int& flag)
{
    int partner = (lane == 31) ? p31 : ((jj == lane) ? 31 : jj);
    jj  = (jj + 1 == 31) ? 0 : jj + 1;
    p31 += 16; if (p31 >= 31) p31 -= 31;

    u64 B1[16], B2[16];
    #pragma unroll
    for (int i = 0; i < 16; i++) B1[i] = __shfl_sync(FULL, A1[i], partner);
    float no1 = __shfl_sync(FULL, n1, partner);
    float go1 = __shfl_sync(FULL, g1, partner);
    #pragma unroll
    for (int i = 0; i < 16; i++) B2[i] = __shfl_sync(FULL, A2[i], partner);
    float no2 = __shfl_sync(FULL, n2, partner);
    float go2 = __shfl_sync(FULL, g2, partner);

    // dots (2 packed accumulators each; identical order on both pair lanes)
    u64 d0 = 0, d1 = 0, e0 = 0, e1 = 0;
    #pragma unroll
    for (int i = 0; i < 16; i += 2) {
        d0 = fma2(A1[i+0], B1[i+0], d0);
        d1 = fma2(A1[i+1], B1[i+1], d1);
        e0 = fma2(A2[i+0], B2[i+0], e0);
        e1 = fma2(A2[i+1], B2[i+1], e1);
    }
    d0 = add2(d0, d1);
    e0 = add2(e0, e1);
    float2 fr1 = unpack2(d0), fr2 = unpack2(e0);
    float apq1 = (fr1.x + fr1.y) * (g1 * go1);
    float apq2 = (fr2.x + fr2.y) * (g2 * go2);

    const bool isp = lane < partner;
    float app1 = isp ? n1 : no1,  aqq1 = isp ? no1 : n1;
    float app2 = isp ? n2 : no2,  aqq2 = isp ? no2 : n2;

    if (TRACK) {
        flag |= (apq1 * apq1 > 1e-6f * (app1 * aqq1));
        flag |= (apq2 * apq2 > 1e-6f * (app2 * aqq2));
    }

    // Branch-free tangent: t = y/(x + copysign(h,x)), h = sqrt(x^2+y^2).
    float x1 = aqq1 - app1, y1 = 2.0f * apq1;
    float x2 = aqq2 - app2, y2 = 2.0f * apq2;
    float h1a = sqrtf(fmaf(x1, x1, y1 * y1));
    float h2a = sqrtf(fmaf(x2, x2, y2 * y2));
    float t1 = __fdividef(y1, x1 + copysignf(h1a + 1e-30f, x1));
    float t2 = __fdividef(y2, x2 + copysignf(h2a + 1e-30f, x2));
    float tO1 = isp ? -t1 : t1;
    float tO2 = isp ? -t2 : t2;
    float h11 = fmaf(t1, t1, 1.0f);
    float h12 = fmaf(t2, t2, 1.0f);
    float c1 = rsqrtf(h11);
    float c2 = rsqrtf(h12);

    n1 = fmaf(tO1, apq1, n1);
    n2 = fmaf(tO2, apq2, n2);
    float co1 = tO1 * go1 * rg1;
    float co2 = tO2 * go2 * rg2;
    g1 *= c1;  rg1 *= h11 * c1;
    g2 *= c2;  rg2 *= h12 * c2;

    u64 C1 = pack2(co1, co1);
    u64 C2 = pack2(co2, co2);
    #pragma unroll
    for (int i = 0; i < 16; i++) {
        A1[i] = fma2(C1, B1[i], A1[i]);
        A2[i] = fma2(C2, B2[i], A2[i]);
    }
}

__device__ __forceinline__ float col_norm2(const u64 (&A)[16])
{
    u64 n0 = 0, n1 = 0;
    #pragma unroll
    for (int i = 0; i < 16; i += 2) {
        n0 = fma2(A[i+0], A[i+0], n0);
        n1 = fma2(A[i+1], A[i+1], n1);
    }
    n0 = add2(n0, n1);
    float2 g = unpack2(n0);
    return g.x + g.y;
}

__device__ __forceinline__ void load_mat(u64 (&A)[16], const float* P, int mat, int lane)
{
    const float4* p4 = reinterpret_cast<const float4*>(P + (size_t)mat * 1024 + lane * 32);
    #pragma unroll
    for (int k = 0; k < 8; k++) {
        float4 v = p4[k];
        A[2*k+0] = pack2(v.x, v.y);
        A[2*k+1] = pack2(v.z, v.w);
    }
}

// Reconstruct X = U diag(log lambda) U^T for one matrix via the warp's smem
// staging buffer (sT[e*34+r] = U[r][e], stride 34 = conflict-free + 8B-aligned).
__device__ __forceinline__ void reconstruct(const u64 (&A)[16], float* sT,
                                            float* out, int mat, int lane)
{
    float norm = col_norm2(A);                  // lambda^2 (true units)
    float invl = rsqrtf(norm);
    float g    = 0.5f * logf(norm);

    float* sg = sT + 32 * 34;
    {
        u64* dst = reinterpret_cast<u64*>(sT + lane * 34);
        u64 IV = pack2(invl, invl);
        #pragma unroll
        for (int i = 0; i < 16; i++) dst[i] = mul2(A[i], IV);
    }
    sg[lane] = g;
    __syncwarp();

    u64 X[16];
    #pragma unroll
    for (int cc = 0; cc < 16; cc++) X[cc] = 0;
    #pragma unroll
    for (int i = 0; i < 32; i++) {
        float coef = sg[i] * sT[i * 34 + lane];                       // conflict-free
        u64 CP = pack2(coef, coef);
        const u64* rowp = reinterpret_cast<const u64*>(sT + i * 34);  // broadcast LDS.64
        #pragma unroll
        for (int cc = 0; cc < 16; cc++)
            X[cc] = fma2(CP, rowp[cc], X[cc]);
    }

    float4* o4 = reinterpret_cast<float4*>(out + (size_t)mat * 1024 + lane * 32);
    #pragma unroll
    for (int k = 0; k < 8; k++) {
        float2 lo = unpack2(X[2*k+0]);
        float2 hi = unpack2(X[2*k+1]);
        o4[k] = make_float4(lo.x, lo.y, hi.x, hi.y);
    }
}

// 2 warps/block, 2 matrices/warp. 6 blocks/SM (170-reg cap) = 12 warps but
// 24 resident matrices; intra-warp ILP (2 streams) hides the SHFL+MUFU
// latency chains that extra warps could not (L1 crossbar contention, R16).
// NOTE: never force regs below the live set (~145 here): R9/R15 showed ptxas
// spills or bloats alu when squeezed.
__global__ __launch_bounds__(64, 6)
void logeig_kernel(const float* __restrict__ P, float* __restrict__ out, int nmat)
{
    __shared__ __align__(16) float sh[2][32 * 34 + 32];
    const int lane = threadIdx.x & 31;
    const int wib  = threadIdx.x >> 5;
    const int m1   = blockIdx.x * 4 + wib * 2;      // first matrix of this warp
    if (m1 >= nmat) return;
    const int  m2v    = m1 + 1;
    const bool valid2 = (m2v < nmat);
    const int  m2     = valid2 ? m2v : m1;          // duplicate m1 if odd tail

    u64 A1[16], A2[16];
    load_mat(A1, P, m1, lane);
    load_mat(A2, P, m2, lane);

    // Incremental tournament state (shared by both matrices):
    // lane<31: partner j = (r - lane) mod 31, ==lane -> pairs with 31.
    // lane 31: partner = 16*r mod 31.
    int jj  = (31 - lane) % 31;
    int p31 = 0;

    float n1 = 0.f, n2 = 0.f;
    int dummy = 0;

    // ---- 3 untracked warm-up sweeps ----
    for (int sweep = 0; sweep < 3; sweep++) {
        n1 = col_norm2(A1);                     // exact norm refresh (true units)
        n2 = col_norm2(A2);
        float g1 = 1.f, g2 = 1.f, rg1 = 1.f, rg2 = 1.f;
        for (int r = 0; r < 31; r++)
            jacobi_round2<false>(A1, A2, n1, n2, g1, g2, rg1, rg2,
                                 lane, jj, p31, dummy);
        u64 G1 = pack2(g1, g1), G2 = pack2(g2, g2);   // back to true units
        #pragma unroll
        for (int i = 0; i < 16; i++) { A1[i] = mul2(A1[i], G1); A2[i] = mul2(A2[i], G2); }
    }

    // ---- tracked sweeps, exit when BOTH matrices converged ----
    for (int sweep = 0; sweep < 7; sweep++) {
        n1 = col_norm2(A1);
        n2 = col_norm2(A2);
        float g1 = 1.f, g2 = 1.f, rg1 = 1.f, rg2 = 1.f;
        int flag = 0;
        for (int r = 0; r < 31; r++)
            jacobi_round2<true>(A1, A2, n1, n2, g1, g2, rg1, rg2,
                                lane, jj, p31, flag);
        u64 G1 = pack2(g1, g1), G2 = pack2(g2, g2);
        #pragma unroll
        for (int i = 0; i < 16; i++) { A1[i] = mul2(A1[i], G1); A2[i] = mul2(A2[i], G2); }
        if (!__any_sync(FULL, flag)) break;
    }

    // ---- Finalize both matrices (sequential; reuse the warp's smem buffer) ----
    float* sT = sh[wib];
    reconstruct(A1, sT, out, m1, lane);
    if (valid2) {
        __syncwarp();
        reconstruct(A2, sT, out, m2v, lane);
    }
}

extern "C" void kernel_launch(void* const* d_in, const int* in_sizes, int n_in,
                              void* d_out, int out_size)
{
    const float* P = (const float*)d_in[0];
    float* out = (float*)d_out;
    int nmat = in_sizes[0] / 1024;               // 32x32 matrices
    int blocks = (nmat + 3) / 4;                 // 4 matrices per block
    logeig_kernel<<<blocks, 64>>>(P, out, nmat);
}